// round 2
// baseline (speedup 1.0000x reference)
#include <cuda_runtime.h>
#include <cuda_bf16.h>

// ---------------- static scratch (no allocations allowed) ----------------
#define N_MAX   65536
#define ET_MAX  2097152   // E + N capacity

__device__ __align__(16) int   g_rowptr[N_MAX + 1];
__device__ __align__(16) int   g_fill[N_MAX];
__device__ __align__(16) int   g_colsrc[ET_MAX];
__device__ __align__(16) float g_act[(size_t)N_MAX * 128];   // layer-1 activations
__device__ __align__(16) float g_h[(size_t)N_MAX * 128];     // layer-2 GEMM output
__device__ __align__(16) float4 g_as[N_MAX];                 // per-node alpha_src (4 heads)
__device__ __align__(16) float4 g_ad[N_MAX];                 // per-node alpha_dst
__device__ __align__(16) float g_h3[N_MAX];
__device__ __align__(16) float g_as3[N_MAX];
__device__ __align__(16) float g_ad3[N_MAX];
__device__ __align__(16) float g_ws1[8];                     // ws1[4], wd1[4]
__device__ int g_is64;

// ---------------- helpers ----------------
__device__ __forceinline__ float leakyf(float x) { return x > 0.f ? x : 0.2f * x; }
__device__ __forceinline__ float eluf(float x)   { return x > 0.f ? x : (__expf(x) - 1.f); }

__device__ __forceinline__ float4 pexp4(float4 as, float4 ad) {
    float4 r;
    r.x = __expf(leakyf(as.x + ad.x));
    r.y = __expf(leakyf(as.y + ad.y));
    r.z = __expf(leakyf(as.z + ad.z));
    r.w = __expf(leakyf(as.w + ad.w));
    return r;
}
__device__ __forceinline__ float selh(float4 v, int h) {
    return h == 0 ? v.x : (h == 1 ? v.y : (h == 2 ? v.z : v.w));
}
__device__ __forceinline__ void red4(float4& v) {
#pragma unroll
    for (int o = 16; o; o >>= 1) {
        v.x += __shfl_xor_sync(0xffffffffu, v.x, o);
        v.y += __shfl_xor_sync(0xffffffffu, v.y, o);
        v.z += __shfl_xor_sync(0xffffffffu, v.z, o);
        v.w += __shfl_xor_sync(0xffffffffu, v.w, o);
    }
}
__device__ __forceinline__ int edge_val(const void* ei, long long idx, int is64) {
    if (is64) return (int)((const long long*)ei)[idx];
    return ((const int*)ei)[idx];
}

// ---------------- CSR build ----------------
__global__ void k_detect(const void* ei, int E) {
    // int64 data has zero high words (values < N << 2^31)
    int n = E < 64 ? E : 64;
    const int* p = (const int*)ei;
    int allz = 1;
    for (int i = 0; i < n; i++)
        if (p[2 * i + 1] != 0) allz = 0;
    g_is64 = allz;
}

__global__ void k_zero(int N) {
    int i = blockIdx.x * blockDim.x + threadIdx.x;
    if (i < N) g_fill[i] = 0;
}

__global__ void k_hist(const void* ei, int E) {
    int i = blockIdx.x * blockDim.x + threadIdx.x;
    if (i >= E) return;
    int is64 = g_is64;
    int d = edge_val(ei, (long long)E + i, is64);
    atomicAdd(&g_fill[d], 1);
}

__global__ void k_scan(int N, int Etot) {
    __shared__ int sh[1024];
    int t = threadIdx.x;
    int chunk = (N + 1023) / 1024;
    int lo = t * chunk; if (lo > N) lo = N;
    int hi = lo + chunk; if (hi > N) hi = N;
    int s = 0;
    for (int i = lo; i < hi; i++) s += g_fill[i] + 1;   // +1 self loop
    sh[t] = s;
    __syncthreads();
    for (int o = 1; o < 1024; o <<= 1) {
        int v = (t >= o) ? sh[t - o] : 0;
        __syncthreads();
        if (t >= o) sh[t] += v;
        __syncthreads();
    }
    int run = t ? sh[t - 1] : 0;
    for (int i = lo; i < hi; i++) {
        int d = g_fill[i] + 1;
        g_rowptr[i] = run;
        g_fill[i] = run;
        run += d;
    }
    if (t == 1023) g_rowptr[N] = Etot;
}

__global__ void k_scatter(const void* ei, int E, int N) {
    int i = blockIdx.x * blockDim.x + threadIdx.x;
    int tot = E + N;
    if (i >= tot) return;
    int is64 = g_is64;
    int s, d;
    if (i < E) {
        s = edge_val(ei, i, is64);
        d = edge_val(ei, (long long)E + i, is64);
    } else {
        s = i - E; d = s;
    }
    int pos = atomicAdd(&g_fill[d], 1);
    g_colsrc[pos] = s;
}

// ---------------- layer 1 ----------------
__global__ void k_ws1(const float* W1, const float* as1, const float* ad1) {
    int h = threadIdx.x;
    if (h >= 4) return;
    float s = 0.f, dd = 0.f;
    for (int c = 0; c < 32; c++) {
        float w = W1[h * 32 + c];
        s  += w * as1[h * 32 + c];
        dd += w * ad1[h * 32 + c];
    }
    g_ws1[h] = s; g_ws1[4 + h] = dd;
}

__global__ void k_as1(const float* x, int N) {
    int n = blockIdx.x * blockDim.x + threadIdx.x;
    if (n >= N) return;
    float xv = x[n];
    float4 ws = *(const float4*)&g_ws1[0];
    float4 wd = *(const float4*)&g_ws1[4];
    g_as[n] = make_float4(xv * ws.x, xv * ws.y, xv * ws.z, xv * ws.w);
    g_ad[n] = make_float4(xv * wd.x, xv * wd.y, xv * wd.z, xv * wd.w);
}

// warp per dst node: t[h] = sum alpha*x[src]; act1 = elu(t[h]*W1 + b1)
__global__ void k_agg1(const float* x, const float* W1, const float* b1, int N) {
    int wid = (blockIdx.x * blockDim.x + threadIdx.x) >> 5;
    int lane = threadIdx.x & 31;
    if (wid >= N) return;
    int lo = g_rowptr[wid], hi = g_rowptr[wid + 1];
    float4 ad = g_ad[wid];
    float4 t  = make_float4(0, 0, 0, 0);
    float4 ss = make_float4(0, 0, 0, 0);
    for (int i = lo + lane; i < hi; i += 32) {
        int s = g_colsrc[i];
        float4 p = pexp4(g_as[s], ad);
        ss.x += p.x; ss.y += p.y; ss.z += p.z; ss.w += p.w;
        float xv = __ldg(&x[s]);
        t.x += p.x * xv; t.y += p.y * xv; t.z += p.z * xv; t.w += p.w * xv;
    }
    red4(t); red4(ss);
    int hd = lane >> 3;
    float th = selh(t, hd) / selh(ss, hd);
    float4 w = *(const float4*)&W1[lane * 4];
    float4 b = *(const float4*)&b1[lane * 4];
    float4 o;
    o.x = eluf(th * w.x + b.x);
    o.y = eluf(th * w.y + b.y);
    o.z = eluf(th * w.z + b.z);
    o.w = eluf(th * w.w + b.w);
    *(float4*)&g_act[(size_t)wid * 128 + lane * 4] = o;
}

// ---------------- layer 2 GEMM: g_h = g_act @ W2  (N x 128 x 128) ----------------
__global__ void k_gemm(const float* __restrict__ B, int N) {
    __shared__ float As[16][64];
    __shared__ float Bs[16][128];
    int tid = threadIdx.x;
    int tx = tid & 31, ty = tid >> 5;
    int row0 = blockIdx.x * 64;
    float acc[8][4];
#pragma unroll
    for (int r = 0; r < 8; r++)
#pragma unroll
        for (int c = 0; c < 4; c++) acc[r][c] = 0.f;

    for (int kt = 0; kt < 8; kt++) {
        {
            int r = tid >> 2;           // 0..63
            int k4 = (tid & 3) * 4;     // 0,4,8,12
            int row = row0 + r;
            float4 av = (row < N)
                ? *(const float4*)&g_act[(size_t)row * 128 + kt * 16 + k4]
                : make_float4(0, 0, 0, 0);
            As[k4 + 0][r] = av.x; As[k4 + 1][r] = av.y;
            As[k4 + 2][r] = av.z; As[k4 + 3][r] = av.w;
        }
#pragma unroll
        for (int rr = 0; rr < 2; rr++) {
            int q = tid + 256 * rr;     // 0..511
            int k = q >> 5;
            int n4 = (q & 31) * 4;
            *(float4*)&Bs[k][n4] = *(const float4*)&B[(size_t)(kt * 16 + k) * 128 + n4];
        }
        __syncthreads();
#pragma unroll
        for (int k = 0; k < 16; k++) {
            float a[8];
            *(float4*)&a[0] = *(float4*)&As[k][ty * 8];
            *(float4*)&a[4] = *(float4*)&As[k][ty * 8 + 4];
            float4 b = *(float4*)&Bs[k][tx * 4];
#pragma unroll
            for (int r = 0; r < 8; r++) {
                acc[r][0] += a[r] * b.x;
                acc[r][1] += a[r] * b.y;
                acc[r][2] += a[r] * b.z;
                acc[r][3] += a[r] * b.w;
            }
        }
        __syncthreads();
    }
#pragma unroll
    for (int r = 0; r < 8; r++) {
        int row = row0 + ty * 8 + r;
        if (row < N)
            *(float4*)&g_h[(size_t)row * 128 + tx * 4] = *(float4*)&acc[r][0];
    }
}

// warp per node: as2/ad2 = per-head dot(h2[n], a_src2/a_dst2)
__global__ void k_alpha2(const float* __restrict__ aw, const float* __restrict__ dw, int N) {
    int n = (blockIdx.x * blockDim.x + threadIdx.x) >> 5;
    int lane = threadIdx.x & 31;
    if (n >= N) return;
    float4 hv = *(const float4*)&g_h[(size_t)n * 128 + lane * 4];
    float4 wa = *(const float4*)&aw[lane * 4];
    float4 wd = *(const float4*)&dw[lane * 4];
    float pa = hv.x * wa.x + hv.y * wa.y + hv.z * wa.z + hv.w * wa.w;
    float pd = hv.x * wd.x + hv.y * wd.y + hv.z * wd.z + hv.w * wd.w;
#pragma unroll
    for (int o = 4; o; o >>= 1) {   // reduce within 8-lane head groups
        pa += __shfl_xor_sync(0xffffffffu, pa, o);
        pd += __shfl_xor_sync(0xffffffffu, pd, o);
    }
    float a0 = __shfl_sync(0xffffffffu, pa, 0);
    float a1 = __shfl_sync(0xffffffffu, pa, 8);
    float a2 = __shfl_sync(0xffffffffu, pa, 16);
    float a3 = __shfl_sync(0xffffffffu, pa, 24);
    float d0 = __shfl_sync(0xffffffffu, pd, 0);
    float d1 = __shfl_sync(0xffffffffu, pd, 8);
    float d2 = __shfl_sync(0xffffffffu, pd, 16);
    float d3 = __shfl_sync(0xffffffffu, pd, 24);
    if (lane == 0) {
        g_as[n] = make_float4(a0, a1, a2, a3);
        g_ad[n] = make_float4(d0, d1, d2, d3);
    }
}

// warp per dst node, chunked p through shared; epilogue fuses layer-3 projection
#define AGG2_WARPS 8
__global__ void k_agg2(const float* __restrict__ b2, const float* __restrict__ W3,
                       const float* __restrict__ a3s, const float* __restrict__ a3d, int N) {
    __shared__ float4 shp[AGG2_WARPS][32];
    __shared__ int    shs[AGG2_WARPS][32];
    int w = threadIdx.x >> 5, lane = threadIdx.x & 31;
    int n = blockIdx.x * AGG2_WARPS + w;
    if (n >= N) return;
    int lo = g_rowptr[n], hi = g_rowptr[n + 1];
    float4 ad = g_ad[n];
    float4 ss = make_float4(0, 0, 0, 0);
    float4 acc = make_float4(0, 0, 0, 0);
    int hd = lane >> 3;
    for (int base = lo; base < hi; base += 32) {
        int i = base + lane;
        if (i < hi) {
            int s = g_colsrc[i];
            float4 p = pexp4(g_as[s], ad);
            ss.x += p.x; ss.y += p.y; ss.z += p.z; ss.w += p.w;
            shp[w][lane] = p;
            shs[w][lane] = s;
        }
        __syncwarp();
        int cnt = hi - base; if (cnt > 32) cnt = 32;
#pragma unroll 4
        for (int j = 0; j < cnt; j++) {
            int s = shs[w][j];
            float ph = selh(shp[w][j], hd);
            float4 hv = *(const float4*)&g_h[(size_t)s * 128 + lane * 4];
            acc.x += ph * hv.x; acc.y += ph * hv.y;
            acc.z += ph * hv.z; acc.w += ph * hv.w;
        }
        __syncwarp();
    }
    red4(ss);
    float inv = 1.f / selh(ss, hd);
    float4 b = *(const float4*)&b2[lane * 4];
    float4 o;
    o.x = eluf(acc.x * inv + b.x);
    o.y = eluf(acc.y * inv + b.y);
    o.z = eluf(acc.z * inv + b.z);
    o.w = eluf(acc.w * inv + b.w);
    // fused layer-3 projection: h3 = act2 . W3
    float4 w3 = *(const float4*)&W3[lane * 4];
    float part = o.x * w3.x + o.y * w3.y + o.z * w3.z + o.w * w3.w;
#pragma unroll
    for (int off = 16; off; off >>= 1) part += __shfl_xor_sync(0xffffffffu, part, off);
    if (lane == 0) {
        g_h3[n]  = part;
        g_as3[n] = part * __ldg(a3s);
        g_ad3[n] = part * __ldg(a3d);
    }
}

// warp per dst node: scalar attention aggregation of h3
__global__ void k_agg3(const float* __restrict__ b3, float* __restrict__ out, int N) {
    int n = (blockIdx.x * blockDim.x + threadIdx.x) >> 5;
    int lane = threadIdx.x & 31;
    if (n >= N) return;
    int lo = g_rowptr[n], hi = g_rowptr[n + 1];
    float adn = g_ad3[n];
    float num = 0.f, den = 0.f;
    for (int i = lo + lane; i < hi; i += 32) {
        int s = g_colsrc[i];
        float p = __expf(leakyf(g_as3[s] + adn));
        num += p * g_h3[s];
        den += p;
    }
#pragma unroll
    for (int o = 16; o; o >>= 1) {
        num += __shfl_xor_sync(0xffffffffu, num, o);
        den += __shfl_xor_sync(0xffffffffu, den, o);
    }
    if (lane == 0) out[n] = num / den + __ldg(b3);
}

// ---------------- launch ----------------
extern "C" void kernel_launch(void* const* d_in, const int* in_sizes, int n_in,
                              void* d_out, int out_size) {
    const float* x   = (const float*)d_in[0];
    const void*  ei  = d_in[1];
    const float* W1  = (const float*)d_in[2];
    const float* as1 = (const float*)d_in[3];
    const float* ad1 = (const float*)d_in[4];
    const float* b1  = (const float*)d_in[5];
    const float* W2  = (const float*)d_in[6];
    const float* as2 = (const float*)d_in[7];
    const float* ad2 = (const float*)d_in[8];
    const float* b2  = (const float*)d_in[9];
    const float* W3  = (const float*)d_in[10];
    const float* a3s = (const float*)d_in[11];
    const float* a3d = (const float*)d_in[12];
    const float* b3  = (const float*)d_in[13];
    float* out = (float*)d_out;

    int N = in_sizes[0];            // IN_C = 1
    int E = in_sizes[1] / 2;        // element count is 2E for both int32/int64
    int Etot = E + N;

    // CSR build
    k_detect<<<1, 1>>>(ei, E);
    k_zero<<<(N + 255) / 256, 256>>>(N);
    k_hist<<<(E + 255) / 256, 256>>>(ei, E);
    k_scan<<<1, 1024>>>(N, Etot);
    k_scatter<<<(Etot + 255) / 256, 256>>>(ei, E, N);

    // layer 1
    k_ws1<<<1, 32>>>(W1, as1, ad1);
    k_as1<<<(N + 255) / 256, 256>>>(x, N);
    k_agg1<<<(N + 7) / 8, 256>>>(x, W1, b1, N);

    // layer 2
    k_gemm<<<(N + 63) / 64, 256>>>(W2, N);
    k_alpha2<<<(N + 7) / 8, 256>>>(as2, ad2, N);
    k_agg2<<<(N + AGG2_WARPS - 1) / AGG2_WARPS, AGG2_WARPS * 32>>>(b2, W3, a3s, a3d, N);

    // layer 3
    k_agg3<<<(N + 7) / 8, 256>>>(b3, out, N);
}

// round 3
// speedup vs baseline: 1.9793x; 1.9793x over previous
#include <cuda_runtime.h>
#include <cuda_bf16.h>

// ---------------- static scratch (no allocations allowed) ----------------
#define N_MAX   65536
#define ET_MAX  2097152   // E + N capacity
#define SCAN_B  512

__device__ __align__(16) int   g_rowptr[N_MAX + 1];
__device__ __align__(16) int   g_fill[N_MAX];
__device__ __align__(16) int   g_colsrc[ET_MAX];
__device__ __align__(16) int   g_bsum[256];
__device__ __align__(16) int   g_boff[256];
__device__ __align__(16) float g_act[(size_t)N_MAX * 128];   // layer-1 activations
__device__ __align__(16) float g_h[(size_t)N_MAX * 128];     // layer-2 GEMM output
__device__ __align__(16) float4 g_as[N_MAX];                 // per-node alpha_src (4 heads)
__device__ __align__(16) float4 g_ad[N_MAX];                 // per-node alpha_dst
__device__ __align__(16) float g_h3[N_MAX];
__device__ __align__(16) float g_as3[N_MAX];
__device__ __align__(16) float g_ad3[N_MAX];
__device__ __align__(16) float g_ws1[8];                     // ws1[4], wd1[4]
__device__ int g_is64;

// ---------------- helpers ----------------
__device__ __forceinline__ float leakyf(float x) { return x > 0.f ? x : 0.2f * x; }
__device__ __forceinline__ float eluf(float x)   { return x > 0.f ? x : (__expf(x) - 1.f); }

__device__ __forceinline__ float4 pexp4(float4 as, float4 ad) {
    float4 r;
    r.x = __expf(leakyf(as.x + ad.x));
    r.y = __expf(leakyf(as.y + ad.y));
    r.z = __expf(leakyf(as.z + ad.z));
    r.w = __expf(leakyf(as.w + ad.w));
    return r;
}
__device__ __forceinline__ float selh(float4 v, int h) {
    return h == 0 ? v.x : (h == 1 ? v.y : (h == 2 ? v.z : v.w));
}
__device__ __forceinline__ void red4(float4& v) {
#pragma unroll
    for (int o = 16; o; o >>= 1) {
        v.x += __shfl_xor_sync(0xffffffffu, v.x, o);
        v.y += __shfl_xor_sync(0xffffffffu, v.y, o);
        v.z += __shfl_xor_sync(0xffffffffu, v.z, o);
        v.w += __shfl_xor_sync(0xffffffffu, v.w, o);
    }
}
__device__ __forceinline__ int edge_val(const void* ei, long long idx, int is64) {
    if (is64) return (int)((const long long*)ei)[idx];
    return ((const int*)ei)[idx];
}

// ---------------- CSR build ----------------
// int64 data has zero high words (all values < N << 2^31). 64 parallel probes.
__global__ void k_detect(const void* ei, int E) {
    __shared__ int bad;
    int t = threadIdx.x;
    if (t == 0) bad = 0;
    __syncthreads();
    int n = E < 64 ? E : 64;
    if (t < n && ((const int*)ei)[2 * t + 1] != 0) bad = 1;
    __syncthreads();
    if (t == 0) g_is64 = !bad;
}

__global__ void k_zero(int N) {
    int i = blockIdx.x * blockDim.x + threadIdx.x;
    if (i < N) g_fill[i] = 0;
}

__global__ void k_hist(const void* ei, int E) {
    int i = blockIdx.x * blockDim.x + threadIdx.x;
    if (i >= E) return;
    int is64 = g_is64;
    int d = edge_val(ei, (long long)E + i, is64);
    atomicAdd(&g_fill[d], 1);
}

// Pass A: per-block sum of (count+1)
__global__ void k_scanA(int N) {
    __shared__ int sh[SCAN_B];
    int t = threadIdx.x;
    int i = blockIdx.x * SCAN_B + t;
    sh[t] = (i < N) ? g_fill[i] + 1 : 0;
    __syncthreads();
#pragma unroll
    for (int o = SCAN_B / 2; o > 0; o >>= 1) {
        if (t < o) sh[t] += sh[t + o];
        __syncthreads();
    }
    if (t == 0) g_bsum[blockIdx.x] = sh[0];
}

// Pass B: exclusive scan over block sums (nb <= 256), single block
__global__ void k_scanB(int nb, int N, int Etot) {
    __shared__ int sh[256];
    int t = threadIdx.x;
    int v = (t < nb) ? g_bsum[t] : 0;
    sh[t] = v;
    __syncthreads();
#pragma unroll
    for (int o = 1; o < 256; o <<= 1) {
        int u = (t >= o) ? sh[t - o] : 0;
        __syncthreads();
        sh[t] += u;
        __syncthreads();
    }
    g_boff[t] = sh[t] - v;   // exclusive
    if (t == 0) g_rowptr[N] = Etot;
}

// Pass C: block-local exclusive scan + block offset -> rowptr / fill
__global__ void k_scanC(int N) {
    __shared__ int sh[SCAN_B];
    int t = threadIdx.x;
    int i = blockIdx.x * SCAN_B + t;
    int v = (i < N) ? g_fill[i] + 1 : 0;
    sh[t] = v;
    __syncthreads();
#pragma unroll
    for (int o = 1; o < SCAN_B; o <<= 1) {
        int u = (t >= o) ? sh[t - o] : 0;
        __syncthreads();
        sh[t] += u;
        __syncthreads();
    }
    if (i < N) {
        int ex = sh[t] - v + g_boff[blockIdx.x];
        g_rowptr[i] = ex;
        g_fill[i] = ex;
    }
}

__global__ void k_scatter(const void* ei, int E, int N) {
    int i = blockIdx.x * blockDim.x + threadIdx.x;
    int tot = E + N;
    if (i >= tot) return;
    int is64 = g_is64;
    int s, d;
    if (i < E) {
        s = edge_val(ei, i, is64);
        d = edge_val(ei, (long long)E + i, is64);
    } else {
        s = i - E; d = s;
    }
    int pos = atomicAdd(&g_fill[d], 1);
    g_colsrc[pos] = s;
}

// ---------------- layer 1 ----------------
__global__ void k_ws1(const float* W1, const float* as1, const float* ad1) {
    int h = threadIdx.x;
    if (h >= 4) return;
    float s = 0.f, dd = 0.f;
    for (int c = 0; c < 32; c++) {
        float w = W1[h * 32 + c];
        s  += w * as1[h * 32 + c];
        dd += w * ad1[h * 32 + c];
    }
    g_ws1[h] = s; g_ws1[4 + h] = dd;
}

__global__ void k_as1(const float* x, int N) {
    int n = blockIdx.x * blockDim.x + threadIdx.x;
    if (n >= N) return;
    float xv = x[n];
    float4 ws = *(const float4*)&g_ws1[0];
    float4 wd = *(const float4*)&g_ws1[4];
    g_as[n] = make_float4(xv * ws.x, xv * ws.y, xv * ws.z, xv * ws.w);
    g_ad[n] = make_float4(xv * wd.x, xv * wd.y, xv * wd.z, xv * wd.w);
}

// warp per dst node: t[h] = sum alpha*x[src]; act1 = elu(t[h]*W1 + b1)
__global__ void k_agg1(const float* x, const float* W1, const float* b1, int N) {
    int wid = (blockIdx.x * blockDim.x + threadIdx.x) >> 5;
    int lane = threadIdx.x & 31;
    if (wid >= N) return;
    int lo = g_rowptr[wid], hi = g_rowptr[wid + 1];
    float4 ad = g_ad[wid];
    float4 t  = make_float4(0, 0, 0, 0);
    float4 ss = make_float4(0, 0, 0, 0);
    for (int i = lo + lane; i < hi; i += 32) {
        int s = g_colsrc[i];
        float4 p = pexp4(g_as[s], ad);
        ss.x += p.x; ss.y += p.y; ss.z += p.z; ss.w += p.w;
        float xv = __ldg(&x[s]);
        t.x += p.x * xv; t.y += p.y * xv; t.z += p.z * xv; t.w += p.w * xv;
    }
    red4(t); red4(ss);
    int hd = lane >> 3;
    float th = selh(t, hd) / selh(ss, hd);
    float4 w = *(const float4*)&W1[lane * 4];
    float4 b = *(const float4*)&b1[lane * 4];
    float4 o;
    o.x = eluf(th * w.x + b.x);
    o.y = eluf(th * w.y + b.y);
    o.z = eluf(th * w.z + b.z);
    o.w = eluf(th * w.w + b.w);
    *(float4*)&g_act[(size_t)wid * 128 + lane * 4] = o;
}

// ---------------- layer 2 GEMM: g_h = g_act @ W2  (N x 128 x 128) ----------------
__global__ void k_gemm(const float* __restrict__ B, int N) {
    __shared__ float As[16][64];
    __shared__ float Bs[16][128];
    int tid = threadIdx.x;
    int tx = tid & 31, ty = tid >> 5;
    int row0 = blockIdx.x * 64;
    float acc[8][4];
#pragma unroll
    for (int r = 0; r < 8; r++)
#pragma unroll
        for (int c = 0; c < 4; c++) acc[r][c] = 0.f;

    for (int kt = 0; kt < 8; kt++) {
        {
            int r = tid >> 2;           // 0..63
            int k4 = (tid & 3) * 4;     // 0,4,8,12
            int row = row0 + r;
            float4 av = (row < N)
                ? *(const float4*)&g_act[(size_t)row * 128 + kt * 16 + k4]
                : make_float4(0, 0, 0, 0);
            As[k4 + 0][r] = av.x; As[k4 + 1][r] = av.y;
            As[k4 + 2][r] = av.z; As[k4 + 3][r] = av.w;
        }
#pragma unroll
        for (int rr = 0; rr < 2; rr++) {
            int q = tid + 256 * rr;     // 0..511
            int k = q >> 5;
            int n4 = (q & 31) * 4;
            *(float4*)&Bs[k][n4] = *(const float4*)&B[(size_t)(kt * 16 + k) * 128 + n4];
        }
        __syncthreads();
#pragma unroll
        for (int k = 0; k < 16; k++) {
            float a[8];
            *(float4*)&a[0] = *(float4*)&As[k][ty * 8];
            *(float4*)&a[4] = *(float4*)&As[k][ty * 8 + 4];
            float4 b = *(float4*)&Bs[k][tx * 4];
#pragma unroll
            for (int r = 0; r < 8; r++) {
                acc[r][0] += a[r] * b.x;
                acc[r][1] += a[r] * b.y;
                acc[r][2] += a[r] * b.z;
                acc[r][3] += a[r] * b.w;
            }
        }
        __syncthreads();
    }
#pragma unroll
    for (int r = 0; r < 8; r++) {
        int row = row0 + ty * 8 + r;
        if (row < N)
            *(float4*)&g_h[(size_t)row * 128 + tx * 4] = *(float4*)&acc[r][0];
    }
}

// warp per node: as2/ad2 = per-head dot(h2[n], a_src2/a_dst2)
__global__ void k_alpha2(const float* __restrict__ aw, const float* __restrict__ dw, int N) {
    int n = (blockIdx.x * blockDim.x + threadIdx.x) >> 5;
    int lane = threadIdx.x & 31;
    if (n >= N) return;
    float4 hv = *(const float4*)&g_h[(size_t)n * 128 + lane * 4];
    float4 wa = *(const float4*)&aw[lane * 4];
    float4 wd = *(const float4*)&dw[lane * 4];
    float pa = hv.x * wa.x + hv.y * wa.y + hv.z * wa.z + hv.w * wa.w;
    float pd = hv.x * wd.x + hv.y * wd.y + hv.z * wd.z + hv.w * wd.w;
#pragma unroll
    for (int o = 4; o; o >>= 1) {   // reduce within 8-lane head groups
        pa += __shfl_xor_sync(0xffffffffu, pa, o);
        pd += __shfl_xor_sync(0xffffffffu, pd, o);
    }
    float a0 = __shfl_sync(0xffffffffu, pa, 0);
    float a1 = __shfl_sync(0xffffffffu, pa, 8);
    float a2 = __shfl_sync(0xffffffffu, pa, 16);
    float a3 = __shfl_sync(0xffffffffu, pa, 24);
    float d0 = __shfl_sync(0xffffffffu, pd, 0);
    float d1 = __shfl_sync(0xffffffffu, pd, 8);
    float d2 = __shfl_sync(0xffffffffu, pd, 16);
    float d3 = __shfl_sync(0xffffffffu, pd, 24);
    if (lane == 0) {
        g_as[n] = make_float4(a0, a1, a2, a3);
        g_ad[n] = make_float4(d0, d1, d2, d3);
    }
}

// warp per dst node, chunked p through shared; epilogue fuses layer-3 projection
#define AGG2_WARPS 8
__global__ void k_agg2(const float* __restrict__ b2, const float* __restrict__ W3,
                       const float* __restrict__ a3s, const float* __restrict__ a3d, int N) {
    __shared__ float4 shp[AGG2_WARPS][32];
    __shared__ int    shs[AGG2_WARPS][32];
    int w = threadIdx.x >> 5, lane = threadIdx.x & 31;
    int n = blockIdx.x * AGG2_WARPS + w;
    if (n >= N) return;
    int lo = g_rowptr[n], hi = g_rowptr[n + 1];
    float4 ad = g_ad[n];
    float4 ss = make_float4(0, 0, 0, 0);
    float4 acc = make_float4(0, 0, 0, 0);
    int hd = lane >> 3;
    for (int base = lo; base < hi; base += 32) {
        int i = base + lane;
        if (i < hi) {
            int s = g_colsrc[i];
            float4 p = pexp4(g_as[s], ad);
            ss.x += p.x; ss.y += p.y; ss.z += p.z; ss.w += p.w;
            shp[w][lane] = p;
            shs[w][lane] = s;
        }
        __syncwarp();
        int cnt = hi - base; if (cnt > 32) cnt = 32;
#pragma unroll 4
        for (int j = 0; j < cnt; j++) {
            int s = shs[w][j];
            float ph = selh(shp[w][j], hd);
            float4 hv = *(const float4*)&g_h[(size_t)s * 128 + lane * 4];
            acc.x += ph * hv.x; acc.y += ph * hv.y;
            acc.z += ph * hv.z; acc.w += ph * hv.w;
        }
        __syncwarp();
    }
    red4(ss);
    float inv = 1.f / selh(ss, hd);
    float4 b = *(const float4*)&b2[lane * 4];
    float4 o;
    o.x = eluf(acc.x * inv + b.x);
    o.y = eluf(acc.y * inv + b.y);
    o.z = eluf(acc.z * inv + b.z);
    o.w = eluf(acc.w * inv + b.w);
    // fused layer-3 projection: h3 = act2 . W3
    float4 w3 = *(const float4*)&W3[lane * 4];
    float part = o.x * w3.x + o.y * w3.y + o.z * w3.z + o.w * w3.w;
#pragma unroll
    for (int off = 16; off; off >>= 1) part += __shfl_xor_sync(0xffffffffu, part, off);
    if (lane == 0) {
        g_h3[n]  = part;
        g_as3[n] = part * __ldg(a3s);
        g_ad3[n] = part * __ldg(a3d);
    }
}

// warp per dst node: scalar attention aggregation of h3
__global__ void k_agg3(const float* __restrict__ b3, float* __restrict__ out, int N) {
    int n = (blockIdx.x * blockDim.x + threadIdx.x) >> 5;
    int lane = threadIdx.x & 31;
    if (n >= N) return;
    int lo = g_rowptr[n], hi = g_rowptr[n + 1];
    float adn = g_ad3[n];
    float num = 0.f, den = 0.f;
    for (int i = lo + lane; i < hi; i += 32) {
        int s = g_colsrc[i];
        float p = __expf(leakyf(g_as3[s] + adn));
        num += p * g_h3[s];
        den += p;
    }
#pragma unroll
    for (int o = 16; o; o >>= 1) {
        num += __shfl_xor_sync(0xffffffffu, num, o);
        den += __shfl_xor_sync(0xffffffffu, den, o);
    }
    if (lane == 0) out[n] = num / den + __ldg(b3);
}

// ---------------- launch ----------------
extern "C" void kernel_launch(void* const* d_in, const int* in_sizes, int n_in,
                              void* d_out, int out_size) {
    const float* x   = (const float*)d_in[0];
    const void*  ei  = d_in[1];
    const float* W1  = (const float*)d_in[2];
    const float* as1 = (const float*)d_in[3];
    const float* ad1 = (const float*)d_in[4];
    const float* b1  = (const float*)d_in[5];
    const float* W2  = (const float*)d_in[6];
    const float* as2 = (const float*)d_in[7];
    const float* ad2 = (const float*)d_in[8];
    const float* b2  = (const float*)d_in[9];
    const float* W3  = (const float*)d_in[10];
    const float* a3s = (const float*)d_in[11];
    const float* a3d = (const float*)d_in[12];
    const float* b3  = (const float*)d_in[13];
    float* out = (float*)d_out;

    int N = in_sizes[0];            // IN_C = 1
    int E = in_sizes[1] / 2;        // element count is 2E for both int32/int64
    int Etot = E + N;
    int nb = (N + SCAN_B - 1) / SCAN_B;

    // CSR build
    k_detect<<<1, 64>>>(ei, E);
    k_zero<<<(N + 255) / 256, 256>>>(N);
    k_hist<<<(E + 255) / 256, 256>>>(ei, E);
    k_scanA<<<nb, SCAN_B>>>(N);
    k_scanB<<<1, 256>>>(nb, N, Etot);
    k_scanC<<<nb, SCAN_B>>>(N);
    k_scatter<<<(Etot + 255) / 256, 256>>>(ei, E, N);

    // layer 1
    k_ws1<<<1, 32>>>(W1, as1, ad1);
    k_as1<<<(N + 255) / 256, 256>>>(x, N);
    k_agg1<<<(N + 7) / 8, 256>>>(x, W1, b1, N);

    // layer 2
    k_gemm<<<(N + 63) / 64, 256>>>(W2, N);
    k_alpha2<<<(N + 7) / 8, 256>>>(as2, ad2, N);
    k_agg2<<<(N + AGG2_WARPS - 1) / AGG2_WARPS, AGG2_WARPS * 32>>>(b2, W3, a3s, a3d, N);

    // layer 3
    k_agg3<<<(N + 7) / 8, 256>>>(b3, out, N);
}

// round 5
// speedup vs baseline: 2.1231x; 1.0727x over previous
#include <cuda_runtime.h>
#include <cuda_bf16.h>

// ---------------- static scratch (no allocations allowed) ----------------
#define N_MAX   65536
#define ET_MAX  2097152   // E + N capacity
#define SCAN_B  512

__device__ __align__(16) int   g_rowptr[N_MAX + 1];
__device__ __align__(16) int   g_fill[N_MAX];
__device__ __align__(16) int   g_colsrc[ET_MAX];
__device__ __align__(16) int   g_bsum[256];
__device__ __align__(16) int   g_boff[256];
__device__ __align__(16) float g_act[(size_t)N_MAX * 128];   // layer-1 activations
__device__ __align__(16) float g_h[(size_t)N_MAX * 128];     // layer-2 GEMM output
__device__ __align__(16) float4 g_as[N_MAX];                 // per-node alpha_src (4 heads)
__device__ __align__(16) float4 g_ad[N_MAX];                 // per-node alpha_dst
__device__ __align__(16) float g_h3[N_MAX];
__device__ __align__(16) float g_as3[N_MAX];
__device__ __align__(16) float g_ad3[N_MAX];
__device__ __align__(16) float g_ws1[8];                     // ws1[4], wd1[4]
__device__ int g_is64;

// ---------------- helpers ----------------
__device__ __forceinline__ float leakyf(float x) { return x > 0.f ? x : 0.2f * x; }
__device__ __forceinline__ float eluf(float x)   { return x > 0.f ? x : (__expf(x) - 1.f); }

__device__ __forceinline__ float4 pexp4(float4 as, float4 ad) {
    float4 r;
    r.x = __expf(leakyf(as.x + ad.x));
    r.y = __expf(leakyf(as.y + ad.y));
    r.z = __expf(leakyf(as.z + ad.z));
    r.w = __expf(leakyf(as.w + ad.w));
    return r;
}
__device__ __forceinline__ float selh(float4 v, int h) {
    return h == 0 ? v.x : (h == 1 ? v.y : (h == 2 ? v.z : v.w));
}
__device__ __forceinline__ void red4(float4& v) {
#pragma unroll
    for (int o = 16; o; o >>= 1) {
        v.x += __shfl_xor_sync(0xffffffffu, v.x, o);
        v.y += __shfl_xor_sync(0xffffffffu, v.y, o);
        v.z += __shfl_xor_sync(0xffffffffu, v.z, o);
        v.w += __shfl_xor_sync(0xffffffffu, v.w, o);
    }
}
__device__ __forceinline__ int edge_val(const void* ei, long long idx, int is64) {
    if (is64) return (int)((const long long*)ei)[idx];
    return ((const int*)ei)[idx];
}

// packed f32x2 ops
__device__ __forceinline__ unsigned long long dup2(float v) {
    unsigned long long r;
    asm("mov.b64 %0, {%1, %1};" : "=l"(r) : "f"(v));
    return r;
}
__device__ __forceinline__ void fma2(unsigned long long& d, unsigned long long a,
                                     unsigned long long b) {
    asm("fma.rn.f32x2 %0, %1, %2, %0;" : "+l"(d) : "l"(a), "l"(b));
}
__device__ __forceinline__ void unpack2(unsigned long long v, float& lo, float& hi) {
    asm("mov.b64 {%0, %1}, %2;" : "=f"(lo), "=f"(hi) : "l"(v));
}

// ---------------- CSR build ----------------
__global__ void k_detect(const void* ei, int E) {
    __shared__ int bad;
    int t = threadIdx.x;
    if (t == 0) bad = 0;
    __syncthreads();
    int n = E < 64 ? E : 64;
    if (t < n && ((const int*)ei)[2 * t + 1] != 0) bad = 1;
    __syncthreads();
    if (t == 0) g_is64 = !bad;
}

__global__ void k_zero(int N) {
    int i = blockIdx.x * blockDim.x + threadIdx.x;
    if (i < N) g_fill[i] = 0;
}

__global__ void k_hist(const void* ei, int E) {
    int i = blockIdx.x * blockDim.x + threadIdx.x;
    if (i >= E) return;
    int is64 = g_is64;
    int d = edge_val(ei, (long long)E + i, is64);
    atomicAdd(&g_fill[d], 1);
}

__global__ void k_scanA(int N) {
    __shared__ int sh[SCAN_B];
    int t = threadIdx.x;
    int i = blockIdx.x * SCAN_B + t;
    sh[t] = (i < N) ? g_fill[i] + 1 : 0;
    __syncthreads();
#pragma unroll
    for (int o = SCAN_B / 2; o > 0; o >>= 1) {
        if (t < o) sh[t] += sh[t + o];
        __syncthreads();
    }
    if (t == 0) g_bsum[blockIdx.x] = sh[0];
}

__global__ void k_scanB(int nb, int N, int Etot) {
    __shared__ int sh[256];
    int t = threadIdx.x;
    int v = (t < nb) ? g_bsum[t] : 0;
    sh[t] = v;
    __syncthreads();
#pragma unroll
    for (int o = 1; o < 256; o <<= 1) {
        int u = (t >= o) ? sh[t - o] : 0;
        __syncthreads();
        sh[t] += u;
        __syncthreads();
    }
    g_boff[t] = sh[t] - v;   // exclusive
    if (t == 0) g_rowptr[N] = Etot;
}

__global__ void k_scanC(int N) {
    __shared__ int sh[SCAN_B];
    int t = threadIdx.x;
    int i = blockIdx.x * SCAN_B + t;
    int v = (i < N) ? g_fill[i] + 1 : 0;
    sh[t] = v;
    __syncthreads();
#pragma unroll
    for (int o = 1; o < SCAN_B; o <<= 1) {
        int u = (t >= o) ? sh[t - o] : 0;
        __syncthreads();
        sh[t] += u;
        __syncthreads();
    }
    if (i < N) {
        int ex = sh[t] - v + g_boff[blockIdx.x];
        g_rowptr[i] = ex;
        g_fill[i] = ex;
    }
}

__global__ void k_scatter(const void* ei, int E, int N) {
    int i = blockIdx.x * blockDim.x + threadIdx.x;
    int tot = E + N;
    if (i >= tot) return;
    int is64 = g_is64;
    int s, d;
    if (i < E) {
        s = edge_val(ei, i, is64);
        d = edge_val(ei, (long long)E + i, is64);
    } else {
        s = i - E; d = s;
    }
    int pos = atomicAdd(&g_fill[d], 1);
    g_colsrc[pos] = s;
}

// ---------------- layer 1 ----------------
__global__ void k_ws1(const float* W1, const float* as1, const float* ad1) {
    int h = threadIdx.x;
    if (h >= 4) return;
    float s = 0.f, dd = 0.f;
    for (int c = 0; c < 32; c++) {
        float w = W1[h * 32 + c];
        s  += w * as1[h * 32 + c];
        dd += w * ad1[h * 32 + c];
    }
    g_ws1[h] = s; g_ws1[4 + h] = dd;
}

__global__ void k_as1(const float* x, int N) {
    int n = blockIdx.x * blockDim.x + threadIdx.x;
    if (n >= N) return;
    float xv = x[n];
    float4 ws = *(const float4*)&g_ws1[0];
    float4 wd = *(const float4*)&g_ws1[4];
    g_as[n] = make_float4(xv * ws.x, xv * ws.y, xv * ws.z, xv * ws.w);
    g_ad[n] = make_float4(xv * wd.x, xv * wd.y, xv * wd.z, xv * wd.w);
}

// warp per dst node: t[h] = sum alpha*x[src]; act1 = elu(t[h]*W1 + b1)
__global__ void k_agg1(const float* x, const float* W1, const float* b1, int N) {
    int wid = (blockIdx.x * blockDim.x + threadIdx.x) >> 5;
    int lane = threadIdx.x & 31;
    if (wid >= N) return;
    int lo = g_rowptr[wid], hi = g_rowptr[wid + 1];
    float4 ad = g_ad[wid];
    float4 t  = make_float4(0, 0, 0, 0);
    float4 ss = make_float4(0, 0, 0, 0);
    for (int i = lo + lane; i < hi; i += 32) {
        int s = g_colsrc[i];
        float4 p = pexp4(g_as[s], ad);
        ss.x += p.x; ss.y += p.y; ss.z += p.z; ss.w += p.w;
        float xv = __ldg(&x[s]);
        t.x += p.x * xv; t.y += p.y * xv; t.z += p.z * xv; t.w += p.w * xv;
    }
    red4(t); red4(ss);
    int hd = lane >> 3;
    float th = selh(t, hd) / selh(ss, hd);
    float4 w = *(const float4*)&W1[lane * 4];
    float4 b = *(const float4*)&b1[lane * 4];
    float4 o;
    o.x = eluf(th * w.x + b.x);
    o.y = eluf(th * w.y + b.y);
    o.z = eluf(th * w.z + b.z);
    o.w = eluf(th * w.w + b.w);
    *(float4*)&g_act[(size_t)wid * 128 + lane * 4] = o;
}

// ---------------- layer 2 GEMM (packed f32x2) + fused alpha2 ----------------
// g_h = g_act @ W2 (N x 128 x 128); epilogue also computes per-head
// alpha_src2/alpha_dst2 dots since each warp holds a full output row.
__global__ void k_gemm(const float* __restrict__ B,
                       const float* __restrict__ aw, const float* __restrict__ dw,
                       int N) {
    __shared__ float As[16][64];
    __shared__ float Bs[16][128];
    int tid = threadIdx.x;
    int tx = tid & 31, ty = tid >> 5;
    int row0 = blockIdx.x * 64;
    unsigned long long acc2[4][4];   // [row-pair][col]; lo=row 2rp, hi=row 2rp+1
#pragma unroll
    for (int rp = 0; rp < 4; rp++)
#pragma unroll
        for (int c = 0; c < 4; c++) acc2[rp][c] = 0ull;

    for (int kt = 0; kt < 8; kt++) {
        {
            int r = tid >> 2;           // 0..63
            int k4 = (tid & 3) * 4;     // 0,4,8,12
            int row = row0 + r;
            float4 av = (row < N)
                ? *(const float4*)&g_act[(size_t)row * 128 + kt * 16 + k4]
                : make_float4(0, 0, 0, 0);
            As[k4 + 0][r] = av.x; As[k4 + 1][r] = av.y;
            As[k4 + 2][r] = av.z; As[k4 + 3][r] = av.w;
        }
#pragma unroll
        for (int rr = 0; rr < 2; rr++) {
            int q = tid + 256 * rr;     // 0..511
            int k = q >> 5;
            int n4 = (q & 31) * 4;
            *(float4*)&Bs[k][n4] = *(const float4*)&B[(size_t)(kt * 16 + k) * 128 + n4];
        }
        __syncthreads();
#pragma unroll
        for (int k = 0; k < 16; k++) {
            unsigned long long a2[4];
#pragma unroll
            for (int rp = 0; rp < 4; rp++)
                a2[rp] = *(const unsigned long long*)&As[k][ty * 8 + rp * 2];
            float4 b = *(const float4*)&Bs[k][tx * 4];
            unsigned long long bd[4];
            bd[0] = dup2(b.x); bd[1] = dup2(b.y);
            bd[2] = dup2(b.z); bd[3] = dup2(b.w);
#pragma unroll
            for (int rp = 0; rp < 4; rp++) {
                fma2(acc2[rp][0], a2[rp], bd[0]);
                fma2(acc2[rp][1], a2[rp], bd[1]);
                fma2(acc2[rp][2], a2[rp], bd[2]);
                fma2(acc2[rp][3], a2[rp], bd[3]);
            }
        }
        __syncthreads();
    }

    float4 wa = *(const float4*)&aw[tx * 4];
    float4 wd4 = *(const float4*)&dw[tx * 4];
#pragma unroll
    for (int rp = 0; rp < 4; rp++) {
        float lo[4], hi[4];
#pragma unroll
        for (int c = 0; c < 4; c++) unpack2(acc2[rp][c], lo[c], hi[c]);
        int rowL = row0 + ty * 8 + rp * 2;
#pragma unroll
        for (int half = 0; half < 2; half++) {
            float* v = half ? hi : lo;
            int row = rowL + half;
            if (row < N)
                *(float4*)&g_h[(size_t)row * 128 + tx * 4] =
                    make_float4(v[0], v[1], v[2], v[3]);
            // fused alpha2 for this row (warp holds the whole row)
            float pa = v[0] * wa.x + v[1] * wa.y + v[2] * wa.z + v[3] * wa.w;
            float pd = v[0] * wd4.x + v[1] * wd4.y + v[2] * wd4.z + v[3] * wd4.w;
#pragma unroll
            for (int o = 4; o; o >>= 1) {
                pa += __shfl_xor_sync(0xffffffffu, pa, o);
                pd += __shfl_xor_sync(0xffffffffu, pd, o);
            }
            float a0 = __shfl_sync(0xffffffffu, pa, 0);
            float a1 = __shfl_sync(0xffffffffu, pa, 8);
            float a2v = __shfl_sync(0xffffffffu, pa, 16);
            float a3 = __shfl_sync(0xffffffffu, pa, 24);
            float d0 = __shfl_sync(0xffffffffu, pd, 0);
            float d1 = __shfl_sync(0xffffffffu, pd, 8);
            float d2 = __shfl_sync(0xffffffffu, pd, 16);
            float d3 = __shfl_sync(0xffffffffu, pd, 24);
            if (tx == 0 && row < N) {
                g_as[row] = make_float4(a0, a1, a2v, a3);
                g_ad[row] = make_float4(d0, d1, d2, d3);
            }
        }
    }
}

// warp per dst node, chunked p through shared; epilogue fuses layer-3 projection
#define AGG2_WARPS 8
__global__ void k_agg2(const float* __restrict__ b2, const float* __restrict__ W3,
                       const float* __restrict__ a3s, const float* __restrict__ a3d, int N) {
    __shared__ float4 shp[AGG2_WARPS][32];
    __shared__ int    shs[AGG2_WARPS][32];
    int w = threadIdx.x >> 5, lane = threadIdx.x & 31;
    int n = blockIdx.x * AGG2_WARPS + w;
    if (n >= N) return;
    int lo = g_rowptr[n], hi = g_rowptr[n + 1];
    float4 ad = g_ad[n];
    float4 ss = make_float4(0, 0, 0, 0);
    float4 acc = make_float4(0, 0, 0, 0);
    int hd = lane >> 3;
    for (int base = lo; base < hi; base += 32) {
        int i = base + lane;
        if (i < hi) {
            int s = g_colsrc[i];
            float4 p = pexp4(g_as[s], ad);
            ss.x += p.x; ss.y += p.y; ss.z += p.z; ss.w += p.w;
            shp[w][lane] = p;
            shs[w][lane] = s;
        }
        __syncwarp();
        int cnt = hi - base; if (cnt > 32) cnt = 32;
#pragma unroll 4
        for (int j = 0; j < cnt; j++) {
            int s = shs[w][j];
            float ph = selh(shp[w][j], hd);
            float4 hv = *(const float4*)&g_h[(size_t)s * 128 + lane * 4];
            acc.x += ph * hv.x; acc.y += ph * hv.y;
            acc.z += ph * hv.z; acc.w += ph * hv.w;
        }
        __syncwarp();
    }
    red4(ss);
    float inv = 1.f / selh(ss, hd);
    float4 b = *(const float4*)&b2[lane * 4];
    float4 o;
    o.x = eluf(acc.x * inv + b.x);
    o.y = eluf(acc.y * inv + b.y);
    o.z = eluf(acc.z * inv + b.z);
    o.w = eluf(acc.w * inv + b.w);
    // fused layer-3 projection: h3 = act2 . W3
    float4 w3 = *(const float4*)&W3[lane * 4];
    float part = o.x * w3.x + o.y * w3.y + o.z * w3.z + o.w * w3.w;
#pragma unroll
    for (int off = 16; off; off >>= 1) part += __shfl_xor_sync(0xffffffffu, part, off);
    if (lane == 0) {
        g_h3[n]  = part;
        g_as3[n] = part * __ldg(a3s);
        g_ad3[n] = part * __ldg(a3d);
    }
}

// warp per dst node: scalar attention aggregation of h3
__global__ void k_agg3(const float* __restrict__ b3, float* __restrict__ out, int N) {
    int n = (blockIdx.x * blockDim.x + threadIdx.x) >> 5;
    int lane = threadIdx.x & 31;
    if (n >= N) return;
    int lo = g_rowptr[n], hi = g_rowptr[n + 1];
    float adn = g_ad3[n];
    float num = 0.f, den = 0.f;
    for (int i = lo + lane; i < hi; i += 32) {
        int s = g_colsrc[i];
        float p = __expf(leakyf(g_as3[s] + adn));
        num += p * g_h3[s];
        den += p;
    }
#pragma unroll
    for (int o = 16; o; o >>= 1) {
        num += __shfl_xor_sync(0xffffffffu, num, o);
        den += __shfl_xor_sync(0xffffffffu, den, o);
    }
    if (lane == 0) out[n] = num / den + __ldg(b3);
}

// ---------------- launch ----------------
extern "C" void kernel_launch(void* const* d_in, const int* in_sizes, int n_in,
                              void* d_out, int out_size) {
    const float* x   = (const float*)d_in[0];
    const void*  ei  = d_in[1];
    const float* W1  = (const float*)d_in[2];
    const float* as1 = (const float*)d_in[3];
    const float* ad1 = (const float*)d_in[4];
    const float* b1  = (const float*)d_in[5];
    const float* W2  = (const float*)d_in[6];
    const float* as2 = (const float*)d_in[7];
    const float* ad2 = (const float*)d_in[8];
    const float* b2  = (const float*)d_in[9];
    const float* W3  = (const float*)d_in[10];
    const float* a3s = (const float*)d_in[11];
    const float* a3d = (const float*)d_in[12];
    const float* b3  = (const float*)d_in[13];
    float* out = (float*)d_out;

    int N = in_sizes[0];            // IN_C = 1
    int E = in_sizes[1] / 2;        // element count is 2E for both int32/int64
    int Etot = E + N;
    int nb = (N + SCAN_B - 1) / SCAN_B;

    // CSR build
    k_detect<<<1, 64>>>(ei, E);
    k_zero<<<(N + 255) / 256, 256>>>(N);
    k_hist<<<(E + 255) / 256, 256>>>(ei, E);
    k_scanA<<<nb, SCAN_B>>>(N);
    k_scanB<<<1, 256>>>(nb, N, Etot);
    k_scanC<<<nb, SCAN_B>>>(N);
    k_scatter<<<(Etot + 255) / 256, 256>>>(ei, E, N);

    // layer 1
    k_ws1<<<1, 32>>>(W1, as1, ad1);
    k_as1<<<(N + 255) / 256, 256>>>(x, N);
    k_agg1<<<(N + 7) / 8, 256>>>(x, W1, b1, N);

    // layer 2 (alpha2 fused into gemm epilogue)
    k_gemm<<<(N + 63) / 64, 256>>>(W2, as2, ad2, N);
    k_agg2<<<(N + AGG2_WARPS - 1) / AGG2_WARPS, AGG2_WARPS * 32>>>(b2, W3, a3s, a3d, N);

    // layer 3
    k_agg3<<<(N + 7) / 8, 256>>>(b3, out, N);
}

// round 7
// speedup vs baseline: 2.4540x; 1.1558x over previous
#include <cuda_runtime.h>
#include <cuda_bf16.h>

// ---------------- static scratch (no allocations allowed) ----------------
#define N_MAX   65536
#define ET_MAX  2097152   // E + N capacity
#define SCAN_B  512

__device__ __align__(16) int   g_rowptr[N_MAX + 1];
__device__ __align__(16) int   g_fill[N_MAX];
__device__ __align__(16) int   g_colsrc[ET_MAX];
__device__ __align__(16) int   g_bsum[256];
__device__ __align__(16) int   g_boff[256];
__device__ __align__(16) float g_act[(size_t)N_MAX * 128];   // layer-1 activations
__device__ __align__(16) float g_h[(size_t)N_MAX * 128];     // layer-2 GEMM output
__device__ __align__(16) float4 g_as[N_MAX];                 // layer-2 alpha_src (4 heads)
__device__ __align__(16) float4 g_ad[N_MAX];                 // layer-2 alpha_dst
__device__ __align__(16) float g_h3[N_MAX];
__device__ int g_is64;

// ---------------- helpers ----------------
__device__ __forceinline__ float leakyf(float x) { return x > 0.f ? x : 0.2f * x; }
__device__ __forceinline__ float eluf(float x)   { return x > 0.f ? x : (__expf(x) - 1.f); }

__device__ __forceinline__ float selh(float4 v, int h) {
    return h == 0 ? v.x : (h == 1 ? v.y : (h == 2 ? v.z : v.w));
}
__device__ __forceinline__ void red4(float4& v) {
#pragma unroll
    for (int o = 16; o; o >>= 1) {
        v.x += __shfl_xor_sync(0xffffffffu, v.x, o);
        v.y += __shfl_xor_sync(0xffffffffu, v.y, o);
        v.z += __shfl_xor_sync(0xffffffffu, v.z, o);
        v.w += __shfl_xor_sync(0xffffffffu, v.w, o);
    }
}
__device__ __forceinline__ int edge_val(const void* ei, long long idx, int is64) {
    if (is64) return (int)((const long long*)ei)[idx];
    return ((const int*)ei)[idx];
}

// packed f32x2 ops
__device__ __forceinline__ unsigned long long dup2(float v) {
    unsigned long long r;
    asm("mov.b64 %0, {%1, %1};" : "=l"(r) : "f"(v));
    return r;
}
__device__ __forceinline__ void fma2(unsigned long long& d, unsigned long long a,
                                     unsigned long long b) {
    asm("fma.rn.f32x2 %0, %1, %2, %0;" : "+l"(d) : "l"(a), "l"(b));
}
__device__ __forceinline__ void unpack2(unsigned long long v, float& lo, float& hi) {
    asm("mov.b64 {%0, %1}, %2;" : "=f"(lo), "=f"(hi) : "l"(v));
}

// ---------------- CSR build ----------------
// k_zero also runs dtype detection in block 0 (int64 => zero high words).
__global__ void k_zero(const void* ei, int E, int N) {
    int i = blockIdx.x * blockDim.x + threadIdx.x;
    if (i < N) g_fill[i] = 0;
    if (blockIdx.x == 0) {
        __shared__ int bad;
        if (threadIdx.x == 0) bad = 0;
        __syncthreads();
        int n = E < 64 ? E : 64;
        if ((int)threadIdx.x < n && ((const int*)ei)[2 * threadIdx.x + 1] != 0) bad = 1;
        __syncthreads();
        if (threadIdx.x == 0) g_is64 = !bad;
    }
}

__global__ void k_hist(const void* ei, int E) {
    int i = blockIdx.x * blockDim.x + threadIdx.x;
    if (i >= E) return;
    int is64 = g_is64;
    int d = edge_val(ei, (long long)E + i, is64);
    atomicAdd(&g_fill[d], 1);
}

__global__ void k_scanA(int N) {
    __shared__ int sh[SCAN_B];
    int t = threadIdx.x;
    int i = blockIdx.x * SCAN_B + t;
    sh[t] = (i < N) ? g_fill[i] + 1 : 0;
    __syncthreads();
#pragma unroll
    for (int o = SCAN_B / 2; o > 0; o >>= 1) {
        if (t < o) sh[t] += sh[t + o];
        __syncthreads();
    }
    if (t == 0) g_bsum[blockIdx.x] = sh[0];
}

__global__ void k_scanB(int nb, int N, int Etot) {
    __shared__ int sh[256];
    int t = threadIdx.x;
    int v = (t < nb) ? g_bsum[t] : 0;
    sh[t] = v;
    __syncthreads();
#pragma unroll
    for (int o = 1; o < 256; o <<= 1) {
        int u = (t >= o) ? sh[t - o] : 0;
        __syncthreads();
        sh[t] += u;
        __syncthreads();
    }
    g_boff[t] = sh[t] - v;   // exclusive
    if (t == 0) g_rowptr[N] = Etot;
}

__global__ void k_scanC(int N) {
    __shared__ int sh[SCAN_B];
    int t = threadIdx.x;
    int i = blockIdx.x * SCAN_B + t;
    int v = (i < N) ? g_fill[i] + 1 : 0;
    sh[t] = v;
    __syncthreads();
#pragma unroll
    for (int o = 1; o < SCAN_B; o <<= 1) {
        int u = (t >= o) ? sh[t - o] : 0;
        __syncthreads();
        sh[t] += u;
        __syncthreads();
    }
    if (i < N) {
        int ex = sh[t] - v + g_boff[blockIdx.x];
        g_rowptr[i] = ex;
        g_fill[i] = ex;
    }
}

__global__ void k_scatter(const void* ei, int E, int N) {
    int i = blockIdx.x * blockDim.x + threadIdx.x;
    int tot = E + N;
    if (i >= tot) return;
    int is64 = g_is64;
    int s, d;
    if (i < E) {
        s = edge_val(ei, i, is64);
        d = edge_val(ei, (long long)E + i, is64);
    } else {
        s = i - E; d = s;
    }
    int pos = atomicAdd(&g_fill[d], 1);
    g_colsrc[pos] = s;
}

// ---------------- layer 1 (fully fused) ----------------
// alpha_src1[n,h] = x[n]*ws[h], alpha_dst1[n,h] = x[n]*wd[h] with
// ws[h] = sum_c W1[h*32+c]*a_src1[h,c] (recomputed per block, cheap).
// warp per dst node: t[h] = sum p*x[src]; act1 = elu((t/s)*W1 + b1)
__global__ void k_agg1(const float* __restrict__ x, const float* __restrict__ W1,
                       const float* __restrict__ as1, const float* __restrict__ ad1,
                       const float* __restrict__ b1, int N) {
    __shared__ float sw[8];   // ws[0..3], wd[0..3]
    int t = threadIdx.x;
    if (t < 8) {
        int h = t & 3;
        const float* av = (t < 4) ? as1 : ad1;
        float s = 0.f;
#pragma unroll
        for (int c = 0; c < 32; c++) s += W1[h * 32 + c] * av[h * 32 + c];
        sw[t] = s;
    }
    __syncthreads();
    int wid = (blockIdx.x * blockDim.x + t) >> 5;
    int lane = t & 31;
    if (wid >= N) return;
    float4 ws = *(const float4*)&sw[0];
    float4 wd = *(const float4*)&sw[4];
    float xd = __ldg(&x[wid]);
    float4 ad = make_float4(xd * wd.x, xd * wd.y, xd * wd.z, xd * wd.w);
    int lo = g_rowptr[wid], hi = g_rowptr[wid + 1];
    float4 tt = make_float4(0, 0, 0, 0);
    float4 ss = make_float4(0, 0, 0, 0);
    for (int i = lo + lane; i < hi; i += 32) {
        int s = g_colsrc[i];
        float xs = __ldg(&x[s]);
        float4 p;
        p.x = __expf(leakyf(xs * ws.x + ad.x));
        p.y = __expf(leakyf(xs * ws.y + ad.y));
        p.z = __expf(leakyf(xs * ws.z + ad.z));
        p.w = __expf(leakyf(xs * ws.w + ad.w));
        ss.x += p.x; ss.y += p.y; ss.z += p.z; ss.w += p.w;
        tt.x += p.x * xs; tt.y += p.y * xs; tt.z += p.z * xs; tt.w += p.w * xs;
    }
    red4(tt); red4(ss);
    int hd = lane >> 3;
    float th = selh(tt, hd) / selh(ss, hd);
    float4 w = *(const float4*)&W1[lane * 4];
    float4 b = *(const float4*)&b1[lane * 4];
    float4 o;
    o.x = eluf(th * w.x + b.x);
    o.y = eluf(th * w.y + b.y);
    o.z = eluf(th * w.z + b.z);
    o.w = eluf(th * w.w + b.w);
    *(float4*)&g_act[(size_t)wid * 128 + lane * 4] = o;
}

// ---------------- layer 2 GEMM (packed f32x2) + fused alpha2 ----------------
__global__ void k_gemm(const float* __restrict__ B,
                       const float* __restrict__ aw, const float* __restrict__ dw,
                       int N) {
    __shared__ float As[16][64];
    __shared__ float Bs[16][128];
    int tid = threadIdx.x;
    int tx = tid & 31, ty = tid >> 5;
    int row0 = blockIdx.x * 64;
    unsigned long long acc2[4][4];   // [row-pair][col]
#pragma unroll
    for (int rp = 0; rp < 4; rp++)
#pragma unroll
        for (int c = 0; c < 4; c++) acc2[rp][c] = 0ull;

    for (int kt = 0; kt < 8; kt++) {
        {
            int r = tid >> 2;
            int k4 = (tid & 3) * 4;
            int row = row0 + r;
            float4 av = (row < N)
                ? *(const float4*)&g_act[(size_t)row * 128 + kt * 16 + k4]
                : make_float4(0, 0, 0, 0);
            As[k4 + 0][r] = av.x; As[k4 + 1][r] = av.y;
            As[k4 + 2][r] = av.z; As[k4 + 3][r] = av.w;
        }
#pragma unroll
        for (int rr = 0; rr < 2; rr++) {
            int q = tid + 256 * rr;
            int k = q >> 5;
            int n4 = (q & 31) * 4;
            *(float4*)&Bs[k][n4] = *(const float4*)&B[(size_t)(kt * 16 + k) * 128 + n4];
        }
        __syncthreads();
#pragma unroll
        for (int k = 0; k < 16; k++) {
            unsigned long long a2[4];
#pragma unroll
            for (int rp = 0; rp < 4; rp++)
                a2[rp] = *(const unsigned long long*)&As[k][ty * 8 + rp * 2];
            float4 b = *(const float4*)&Bs[k][tx * 4];
            unsigned long long bd[4];
            bd[0] = dup2(b.x); bd[1] = dup2(b.y);
            bd[2] = dup2(b.z); bd[3] = dup2(b.w);
#pragma unroll
            for (int rp = 0; rp < 4; rp++) {
                fma2(acc2[rp][0], a2[rp], bd[0]);
                fma2(acc2[rp][1], a2[rp], bd[1]);
                fma2(acc2[rp][2], a2[rp], bd[2]);
                fma2(acc2[rp][3], a2[rp], bd[3]);
            }
        }
        __syncthreads();
    }

    float4 wa = *(const float4*)&aw[tx * 4];
    float4 wd4 = *(const float4*)&dw[tx * 4];
#pragma unroll
    for (int rp = 0; rp < 4; rp++) {
        float lo[4], hi[4];
#pragma unroll
        for (int c = 0; c < 4; c++) unpack2(acc2[rp][c], lo[c], hi[c]);
        int rowL = row0 + ty * 8 + rp * 2;
#pragma unroll
        for (int half = 0; half < 2; half++) {
            float* v = half ? hi : lo;
            int row = rowL + half;
            if (row < N)
                *(float4*)&g_h[(size_t)row * 128 + tx * 4] =
                    make_float4(v[0], v[1], v[2], v[3]);
            float pa = v[0] * wa.x + v[1] * wa.y + v[2] * wa.z + v[3] * wa.w;
            float pd = v[0] * wd4.x + v[1] * wd4.y + v[2] * wd4.z + v[3] * wd4.w;
#pragma unroll
            for (int o = 4; o; o >>= 1) {
                pa += __shfl_xor_sync(0xffffffffu, pa, o);
                pd += __shfl_xor_sync(0xffffffffu, pd, o);
            }
            float a0 = __shfl_sync(0xffffffffu, pa, 0);
            float a1 = __shfl_sync(0xffffffffu, pa, 8);
            float a2v = __shfl_sync(0xffffffffu, pa, 16);
            float a3 = __shfl_sync(0xffffffffu, pa, 24);
            float d0 = __shfl_sync(0xffffffffu, pd, 0);
            float d1 = __shfl_sync(0xffffffffu, pd, 8);
            float d2 = __shfl_sync(0xffffffffu, pd, 16);
            float d3 = __shfl_sync(0xffffffffu, pd, 24);
            if (tx == 0 && row < N) {
                g_as[row] = make_float4(a0, a1, a2v, a3);
                g_ad[row] = make_float4(d0, d1, d2, d3);
            }
        }
    }
}

// ---------------- layer 2 aggregation (+ fused layer-3 projection) ----------------
#define AGG2_WARPS 8
__global__ void k_agg2(const float* __restrict__ b2, const float* __restrict__ W3,
                       int N) {
    __shared__ float shp[AGG2_WARPS][4][33];   // p transposed [head][slot], pad 33
    __shared__ int   shs[AGG2_WARPS][32];
    int w = threadIdx.x >> 5, lane = threadIdx.x & 31;
    int n = blockIdx.x * AGG2_WARPS + w;
    if (n >= N) return;
    int lo = g_rowptr[n], hi = g_rowptr[n + 1];
    float4 ad = g_ad[n];
    float4 ss = make_float4(0, 0, 0, 0);
    float4 acc = make_float4(0, 0, 0, 0);
    int hd = lane >> 3;
    const float* prow = &shp[w][hd][0];
    for (int base = lo; base < hi; base += 32) {
        int i = base + lane;
        if (i < hi) {
            int s = g_colsrc[i];
            float4 as = g_as[s];
            float4 p;
            p.x = __expf(leakyf(as.x + ad.x));
            p.y = __expf(leakyf(as.y + ad.y));
            p.z = __expf(leakyf(as.z + ad.z));
            p.w = __expf(leakyf(as.w + ad.w));
            ss.x += p.x; ss.y += p.y; ss.z += p.z; ss.w += p.w;
            shp[w][0][lane] = p.x;
            shp[w][1][lane] = p.y;
            shp[w][2][lane] = p.z;
            shp[w][3][lane] = p.w;
            shs[w][lane] = s;
        }
        __syncwarp();
        int cnt = hi - base; if (cnt > 32) cnt = 32;
#pragma unroll 4
        for (int j = 0; j < cnt; j++) {
            int s = shs[w][j];
            float ph = prow[j];
            float4 hv = *(const float4*)&g_h[(size_t)s * 128 + lane * 4];
            acc.x += ph * hv.x; acc.y += ph * hv.y;
            acc.z += ph * hv.z; acc.w += ph * hv.w;
        }
        __syncwarp();
    }
    red4(ss);
    float inv = 1.f / selh(ss, hd);
    float4 b = *(const float4*)&b2[lane * 4];
    float4 o;
    o.x = eluf(acc.x * inv + b.x);
    o.y = eluf(acc.y * inv + b.y);
    o.z = eluf(acc.z * inv + b.z);
    o.w = eluf(acc.w * inv + b.w);
    // fused layer-3 projection: h3 = act2 . W3
    float4 w3 = *(const float4*)&W3[lane * 4];
    float part = o.x * w3.x + o.y * w3.y + o.z * w3.z + o.w * w3.w;
#pragma unroll
    for (int off = 16; off; off >>= 1) part += __shfl_xor_sync(0xffffffffu, part, off);
    if (lane == 0) g_h3[n] = part;
}

// ---------------- layer 3 aggregation ----------------
// alpha_src3[s] = h3[s]*a3s, alpha_dst3[n] = h3[n]*a3d (scalars) — inline.
__global__ void k_agg3(const float* __restrict__ a3s, const float* __restrict__ a3d,
                       const float* __restrict__ b3, float* __restrict__ out, int N) {
    int n = (blockIdx.x * blockDim.x + threadIdx.x) >> 5;
    int lane = threadIdx.x & 31;
    if (n >= N) return;
    float sa = __ldg(a3s), sd = __ldg(a3d);
    int lo = g_rowptr[n], hi = g_rowptr[n + 1];
    float adn = g_h3[n] * sd;
    float num = 0.f, den = 0.f;
    for (int i = lo + lane; i < hi; i += 32) {
        int s = g_colsrc[i];
        float h3s = g_h3[s];
        float p = __expf(leakyf(h3s * sa + adn));
        num += p * h3s;
        den += p;
    }
#pragma unroll
    for (int o = 16; o; o >>= 1) {
        num += __shfl_xor_sync(0xffffffffu, num, o);
        den += __shfl_xor_sync(0xffffffffu, den, o);
    }
    if (lane == 0) out[n] = num / den + __ldg(b3);
}

// ---------------- launch ----------------
extern "C" void kernel_launch(void* const* d_in, const int* in_sizes, int n_in,
                              void* d_out, int out_size) {
    const float* x   = (const float*)d_in[0];
    const void*  ei  = d_in[1];
    const float* W1  = (const float*)d_in[2];
    const float* as1 = (const float*)d_in[3];
    const float* ad1 = (const float*)d_in[4];
    const float* b1  = (const float*)d_in[5];
    const float* W2  = (const float*)d_in[6];
    const float* as2 = (const float*)d_in[7];
    const float* ad2 = (const float*)d_in[8];
    const float* b2  = (const float*)d_in[9];
    const float* W3  = (const float*)d_in[10];
    const float* a3s = (const float*)d_in[11];
    const float* a3d = (const float*)d_in[12];
    const float* b3  = (const float*)d_in[13];
    float* out = (float*)d_out;

    int N = in_sizes[0];            // IN_C = 1
    int E = in_sizes[1] / 2;        // element count is 2E for both int32/int64
    int Etot = E + N;
    int nb = (N + SCAN_B - 1) / SCAN_B;

    // CSR build
    k_zero<<<(N + 255) / 256, 256>>>(ei, E, N);
    k_hist<<<(E + 255) / 256, 256>>>(ei, E);
    k_scanA<<<nb, SCAN_B>>>(N);
    k_scanB<<<1, 256>>>(nb, N, Etot);
    k_scanC<<<nb, SCAN_B>>>(N);
    k_scatter<<<(Etot + 255) / 256, 256>>>(ei, E, N);

    // layer 1 (alphas computed on the fly)
    k_agg1<<<(N + 7) / 8, 256>>>(x, W1, as1, ad1, b1, N);

    // layer 2 (alpha2 fused into gemm epilogue)
    k_gemm<<<(N + 63) / 64, 256>>>(W2, as2, ad2, N);
    k_agg2<<<(N + AGG2_WARPS - 1) / AGG2_WARPS, AGG2_WARPS * 32>>>(b2, W3, N);

    // layer 3 (alphas inline)
    k_agg3<<<(N + 7) / 8, 256>>>(a3s, a3d, b3, out, N);
}

// round 8
// speedup vs baseline: 2.5327x; 1.0321x over previous
#include <cuda_runtime.h>
#include <cuda_bf16.h>
#include <cuda_fp16.h>

// ---------------- static scratch (no allocations allowed) ----------------
#define N_MAX   65536
#define ET_MAX  2097152   // E + N capacity
#define SCAN_B  512

__device__ __align__(16) int   g_rowptr[N_MAX + 1];
__device__ __align__(16) int   g_fill[N_MAX];
__device__ __align__(16) int   g_colsrc[ET_MAX];
__device__ __align__(16) int   g_bsum[256];
__device__ __align__(16) float g_act[(size_t)N_MAX * 128];   // layer-1 activations
__device__ __align__(16) __half g_hb[(size_t)N_MAX * 128];   // layer-2 GEMM output (fp16)
__device__ __align__(16) float4 g_as[N_MAX];                 // layer-2 alpha_src (4 heads)
__device__ __align__(16) float4 g_ad[N_MAX];                 // layer-2 alpha_dst
__device__ __align__(16) float g_h3[N_MAX];
__device__ int g_is64;

// ---------------- helpers ----------------
__device__ __forceinline__ float leakyf(float x) { return x > 0.f ? x : 0.2f * x; }
__device__ __forceinline__ float eluf(float x)   { return x > 0.f ? x : (__expf(x) - 1.f); }

__device__ __forceinline__ float selh(float4 v, int h) {
    return h == 0 ? v.x : (h == 1 ? v.y : (h == 2 ? v.z : v.w));
}
__device__ __forceinline__ void red4(float4& v) {
#pragma unroll
    for (int o = 16; o; o >>= 1) {
        v.x += __shfl_xor_sync(0xffffffffu, v.x, o);
        v.y += __shfl_xor_sync(0xffffffffu, v.y, o);
        v.z += __shfl_xor_sync(0xffffffffu, v.z, o);
        v.w += __shfl_xor_sync(0xffffffffu, v.w, o);
    }
}
__device__ __forceinline__ int edge_val(const void* ei, long long idx, int is64) {
    if (is64) return (int)((const long long*)ei)[idx];
    return ((const int*)ei)[idx];
}

// packed f32x2 ops
__device__ __forceinline__ unsigned long long dup2(float v) {
    unsigned long long r;
    asm("mov.b64 %0, {%1, %1};" : "=l"(r) : "f"(v));
    return r;
}
__device__ __forceinline__ void fma2(unsigned long long& d, unsigned long long a,
                                     unsigned long long b) {
    asm("fma.rn.f32x2 %0, %1, %2, %0;" : "+l"(d) : "l"(a), "l"(b));
}
__device__ __forceinline__ void unpack2(unsigned long long v, float& lo, float& hi) {
    asm("mov.b64 {%0, %1}, %2;" : "=f"(lo), "=f"(hi) : "l"(v));
}

// ---------------- CSR build ----------------
// k_zero also: dtype detection (block 0) and rowptr[N] = Etot.
__global__ void k_zero(const void* ei, int E, int N, int Etot) {
    int i = blockIdx.x * blockDim.x + threadIdx.x;
    if (i < N) g_fill[i] = 0;
    if (i == 0) g_rowptr[N] = Etot;
    if (blockIdx.x == 0) {
        __shared__ int bad;
        if (threadIdx.x == 0) bad = 0;
        __syncthreads();
        int n = E < 64 ? E : 64;
        if ((int)threadIdx.x < n && ((const int*)ei)[2 * threadIdx.x + 1] != 0) bad = 1;
        __syncthreads();
        if (threadIdx.x == 0) g_is64 = !bad;
    }
}

__global__ void k_hist(const void* ei, int E) {
    int i = blockIdx.x * blockDim.x + threadIdx.x;
    if (i >= E) return;
    int is64 = g_is64;
    int d = edge_val(ei, (long long)E + i, is64);
    atomicAdd(&g_fill[d], 1);
}

__global__ void k_scanA(int N) {
    __shared__ int sh[SCAN_B];
    int t = threadIdx.x;
    int i = blockIdx.x * SCAN_B + t;
    sh[t] = (i < N) ? g_fill[i] + 1 : 0;
    __syncthreads();
#pragma unroll
    for (int o = SCAN_B / 2; o > 0; o >>= 1) {
        if (t < o) sh[t] += sh[t + o];
        __syncthreads();
    }
    if (t == 0) g_bsum[blockIdx.x] = sh[0];
}

// block-local exclusive scan + self-computed block offset (merged old scanB)
__global__ void k_scanC(int N, int nb) {
    __shared__ int sh[SCAN_B];
    __shared__ int pre[128];
    int t = threadIdx.x;
    int b = blockIdx.x;
    if (t < 128) pre[t] = (t < nb && t < b) ? g_bsum[t] : 0;
    __syncthreads();
#pragma unroll
    for (int o = 64; o > 0; o >>= 1) {
        if (t < o) pre[t] += pre[t + o];
        __syncthreads();
    }
    int boff = pre[0];
    int i = b * SCAN_B + t;
    int v = (i < N) ? g_fill[i] + 1 : 0;
    sh[t] = v;
    __syncthreads();
#pragma unroll
    for (int o = 1; o < SCAN_B; o <<= 1) {
        int u = (t >= o) ? sh[t - o] : 0;
        __syncthreads();
        sh[t] += u;
        __syncthreads();
    }
    if (i < N) {
        int ex = sh[t] - v + boff;
        g_rowptr[i] = ex;
        g_fill[i] = ex;
    }
}

__global__ void k_scatter(const void* ei, int E, int N) {
    int i = blockIdx.x * blockDim.x + threadIdx.x;
    int tot = E + N;
    if (i >= tot) return;
    int is64 = g_is64;
    int s, d;
    if (i < E) {
        s = edge_val(ei, i, is64);
        d = edge_val(ei, (long long)E + i, is64);
    } else {
        s = i - E; d = s;
    }
    int pos = atomicAdd(&g_fill[d], 1);
    g_colsrc[pos] = s;
}

// ---------------- layer 1 (fully fused) ----------------
__global__ void k_agg1(const float* __restrict__ x, const float* __restrict__ W1,
                       const float* __restrict__ as1, const float* __restrict__ ad1,
                       const float* __restrict__ b1, int N) {
    __shared__ float sw[8];   // ws[0..3], wd[0..3]
    int t = threadIdx.x;
    if (t < 8) {
        int h = t & 3;
        const float* av = (t < 4) ? as1 : ad1;
        float s = 0.f;
#pragma unroll
        for (int c = 0; c < 32; c++) s += W1[h * 32 + c] * av[h * 32 + c];
        sw[t] = s;
    }
    __syncthreads();
    int wid = (blockIdx.x * blockDim.x + t) >> 5;
    int lane = t & 31;
    if (wid >= N) return;
    float4 ws = *(const float4*)&sw[0];
    float4 wd = *(const float4*)&sw[4];
    float xd = __ldg(&x[wid]);
    float4 ad = make_float4(xd * wd.x, xd * wd.y, xd * wd.z, xd * wd.w);
    int lo = g_rowptr[wid], hi = g_rowptr[wid + 1];
    float4 tt = make_float4(0, 0, 0, 0);
    float4 ss = make_float4(0, 0, 0, 0);
    for (int i = lo + lane; i < hi; i += 32) {
        int s = g_colsrc[i];
        float xs = __ldg(&x[s]);
        float4 p;
        p.x = __expf(leakyf(xs * ws.x + ad.x));
        p.y = __expf(leakyf(xs * ws.y + ad.y));
        p.z = __expf(leakyf(xs * ws.z + ad.z));
        p.w = __expf(leakyf(xs * ws.w + ad.w));
        ss.x += p.x; ss.y += p.y; ss.z += p.z; ss.w += p.w;
        tt.x += p.x * xs; tt.y += p.y * xs; tt.z += p.z * xs; tt.w += p.w * xs;
    }
    red4(tt); red4(ss);
    int hd = lane >> 3;
    float th = selh(tt, hd) / selh(ss, hd);
    float4 w = *(const float4*)&W1[lane * 4];
    float4 b = *(const float4*)&b1[lane * 4];
    float4 o;
    o.x = eluf(th * w.x + b.x);
    o.y = eluf(th * w.y + b.y);
    o.z = eluf(th * w.z + b.z);
    o.w = eluf(th * w.w + b.w);
    *(float4*)&g_act[(size_t)wid * 128 + lane * 4] = o;
}

// ---------------- layer 2 GEMM (packed f32x2) + fused alpha2, fp16 output ----------------
__global__ void k_gemm(const float* __restrict__ B,
                       const float* __restrict__ aw, const float* __restrict__ dw,
                       int N) {
    __shared__ float As[16][64];
    __shared__ float Bs[16][128];
    int tid = threadIdx.x;
    int tx = tid & 31, ty = tid >> 5;
    int row0 = blockIdx.x * 64;
    unsigned long long acc2[4][4];   // [row-pair][col]
#pragma unroll
    for (int rp = 0; rp < 4; rp++)
#pragma unroll
        for (int c = 0; c < 4; c++) acc2[rp][c] = 0ull;

    for (int kt = 0; kt < 8; kt++) {
        {
            int r = tid >> 2;
            int k4 = (tid & 3) * 4;
            int row = row0 + r;
            float4 av = (row < N)
                ? *(const float4*)&g_act[(size_t)row * 128 + kt * 16 + k4]
                : make_float4(0, 0, 0, 0);
            As[k4 + 0][r] = av.x; As[k4 + 1][r] = av.y;
            As[k4 + 2][r] = av.z; As[k4 + 3][r] = av.w;
        }
#pragma unroll
        for (int rr = 0; rr < 2; rr++) {
            int q = tid + 256 * rr;
            int k = q >> 5;
            int n4 = (q & 31) * 4;
            *(float4*)&Bs[k][n4] = *(const float4*)&B[(size_t)(kt * 16 + k) * 128 + n4];
        }
        __syncthreads();
#pragma unroll
        for (int k = 0; k < 16; k++) {
            unsigned long long a2[4];
#pragma unroll
            for (int rp = 0; rp < 4; rp++)
                a2[rp] = *(const unsigned long long*)&As[k][ty * 8 + rp * 2];
            float4 b = *(const float4*)&Bs[k][tx * 4];
            unsigned long long bd[4];
            bd[0] = dup2(b.x); bd[1] = dup2(b.y);
            bd[2] = dup2(b.z); bd[3] = dup2(b.w);
#pragma unroll
            for (int rp = 0; rp < 4; rp++) {
                fma2(acc2[rp][0], a2[rp], bd[0]);
                fma2(acc2[rp][1], a2[rp], bd[1]);
                fma2(acc2[rp][2], a2[rp], bd[2]);
                fma2(acc2[rp][3], a2[rp], bd[3]);
            }
        }
        __syncthreads();
    }

    float4 wa = *(const float4*)&aw[tx * 4];
    float4 wd4 = *(const float4*)&dw[tx * 4];
#pragma unroll
    for (int rp = 0; rp < 4; rp++) {
        float lo[4], hi[4];
#pragma unroll
        for (int c = 0; c < 4; c++) unpack2(acc2[rp][c], lo[c], hi[c]);
        int rowL = row0 + ty * 8 + rp * 2;
#pragma unroll
        for (int half = 0; half < 2; half++) {
            float* v = half ? hi : lo;
            int row = rowL + half;
            if (row < N) {
                __half2 h0 = __floats2half2_rn(v[0], v[1]);
                __half2 h1 = __floats2half2_rn(v[2], v[3]);
                uint2 u;
                u.x = *reinterpret_cast<unsigned*>(&h0);
                u.y = *reinterpret_cast<unsigned*>(&h1);
                *(uint2*)&g_hb[(size_t)row * 128 + tx * 4] = u;
            }
            float pa = v[0] * wa.x + v[1] * wa.y + v[2] * wa.z + v[3] * wa.w;
            float pd = v[0] * wd4.x + v[1] * wd4.y + v[2] * wd4.z + v[3] * wd4.w;
#pragma unroll
            for (int o = 4; o; o >>= 1) {
                pa += __shfl_xor_sync(0xffffffffu, pa, o);
                pd += __shfl_xor_sync(0xffffffffu, pd, o);
            }
            float a0 = __shfl_sync(0xffffffffu, pa, 0);
            float a1 = __shfl_sync(0xffffffffu, pa, 8);
            float a2v = __shfl_sync(0xffffffffu, pa, 16);
            float a3 = __shfl_sync(0xffffffffu, pa, 24);
            float d0 = __shfl_sync(0xffffffffu, pd, 0);
            float d1 = __shfl_sync(0xffffffffu, pd, 8);
            float d2 = __shfl_sync(0xffffffffu, pd, 16);
            float d3 = __shfl_sync(0xffffffffu, pd, 24);
            if (tx == 0 && row < N) {
                g_as[row] = make_float4(a0, a1, a2v, a3);
                g_ad[row] = make_float4(d0, d1, d2, d3);
            }
        }
    }
}

// ---------------- layer 2 aggregation (fp16 gather) + fused layer-3 projection ----------------
#define AGG2_WARPS 8
__global__ void k_agg2(const float* __restrict__ b2, const float* __restrict__ W3,
                       int N) {
    __shared__ float shp[AGG2_WARPS][4][33];   // p transposed [head][slot]
    __shared__ int   shs[AGG2_WARPS][32];
    int w = threadIdx.x >> 5, lane = threadIdx.x & 31;
    int n = blockIdx.x * AGG2_WARPS + w;
    if (n >= N) return;
    int lo = g_rowptr[n], hi = g_rowptr[n + 1];
    float4 ad = g_ad[n];
    float4 ss = make_float4(0, 0, 0, 0);
    float4 acc = make_float4(0, 0, 0, 0);
    int hd = lane >> 3;
    const float* prow = &shp[w][hd][0];
    for (int base = lo; base < hi; base += 32) {
        int i = base + lane;
        if (i < hi) {
            int s = g_colsrc[i];
            float4 as = g_as[s];
            float4 p;
            p.x = __expf(leakyf(as.x + ad.x));
            p.y = __expf(leakyf(as.y + ad.y));
            p.z = __expf(leakyf(as.z + ad.z));
            p.w = __expf(leakyf(as.w + ad.w));
            ss.x += p.x; ss.y += p.y; ss.z += p.z; ss.w += p.w;
            shp[w][0][lane] = p.x;
            shp[w][1][lane] = p.y;
            shp[w][2][lane] = p.z;
            shp[w][3][lane] = p.w;
            shs[w][lane] = s;
        }
        __syncwarp();
        int cnt = hi - base; if (cnt > 32) cnt = 32;
#pragma unroll 4
        for (int j = 0; j < cnt; j++) {
            int s = shs[w][j];
            float ph = prow[j];
            uint2 u = *(const uint2*)&g_hb[(size_t)s * 128 + lane * 4];
            __half2 h0 = *reinterpret_cast<__half2*>(&u.x);
            __half2 h1 = *reinterpret_cast<__half2*>(&u.y);
            float2 f0 = __half22float2(h0);
            float2 f1 = __half22float2(h1);
            acc.x += ph * f0.x; acc.y += ph * f0.y;
            acc.z += ph * f1.x; acc.w += ph * f1.y;
        }
        __syncwarp();
    }
    red4(ss);
    float inv = 1.f / selh(ss, hd);
    float4 b = *(const float4*)&b2[lane * 4];
    float4 o;
    o.x = eluf(acc.x * inv + b.x);
    o.y = eluf(acc.y * inv + b.y);
    o.z = eluf(acc.z * inv + b.z);
    o.w = eluf(acc.w * inv + b.w);
    // fused layer-3 projection: h3 = act2 . W3
    float4 w3 = *(const float4*)&W3[lane * 4];
    float part = o.x * w3.x + o.y * w3.y + o.z * w3.z + o.w * w3.w;
#pragma unroll
    for (int off = 16; off; off >>= 1) part += __shfl_xor_sync(0xffffffffu, part, off);
    if (lane == 0) g_h3[n] = part;
}

// ---------------- layer 3 aggregation ----------------
__global__ void k_agg3(const float* __restrict__ a3s, const float* __restrict__ a3d,
                       const float* __restrict__ b3, float* __restrict__ out, int N) {
    int n = (blockIdx.x * blockDim.x + threadIdx.x) >> 5;
    int lane = threadIdx.x & 31;
    if (n >= N) return;
    float sa = __ldg(a3s), sd = __ldg(a3d);
    int lo = g_rowptr[n], hi = g_rowptr[n + 1];
    float adn = g_h3[n] * sd;
    float num = 0.f, den = 0.f;
    for (int i = lo + lane; i < hi; i += 32) {
        int s = g_colsrc[i];
        float h3s = g_h3[s];
        float p = __expf(leakyf(h3s * sa + adn));
        num += p * h3s;
        den += p;
    }
#pragma unroll
    for (int o = 16; o; o >>= 1) {
        num += __shfl_xor_sync(0xffffffffu, num, o);
        den += __shfl_xor_sync(0xffffffffu, den, o);
    }
    if (lane == 0) out[n] = num / den + __ldg(b3);
}

// ---------------- launch ----------------
extern "C" void kernel_launch(void* const* d_in, const int* in_sizes, int n_in,
                              void* d_out, int out_size) {
    const float* x   = (const float*)d_in[0];
    const void*  ei  = d_in[1];
    const float* W1  = (const float*)d_in[2];
    const float* as1 = (const float*)d_in[3];
    const float* ad1 = (const float*)d_in[4];
    const float* b1  = (const float*)d_in[5];
    const float* W2  = (const float*)d_in[6];
    const float* as2 = (const float*)d_in[7];
    const float* ad2 = (const float*)d_in[8];
    const float* b2  = (const float*)d_in[9];
    const float* W3  = (const float*)d_in[10];
    const float* a3s = (const float*)d_in[11];
    const float* a3d = (const float*)d_in[12];
    const float* b3  = (const float*)d_in[13];
    float* out = (float*)d_out;

    int N = in_sizes[0];            // IN_C = 1
    int E = in_sizes[1] / 2;        // element count is 2E for both int32/int64
    int Etot = E + N;
    int nb = (N + SCAN_B - 1) / SCAN_B;

    // CSR build
    k_zero<<<(N + 255) / 256, 256>>>(ei, E, N, Etot);
    k_hist<<<(E + 255) / 256, 256>>>(ei, E);
    k_scanA<<<nb, SCAN_B>>>(N);
    k_scanC<<<nb, SCAN_B>>>(N, nb);
    k_scatter<<<(Etot + 255) / 256, 256>>>(ei, E, N);

    // layer 1 (alphas computed on the fly)
    k_agg1<<<(N + 7) / 8, 256>>>(x, W1, as1, ad1, b1, N);

    // layer 2 (alpha2 fused into gemm epilogue, fp16 h)
    k_gemm<<<(N + 63) / 64, 256>>>(W2, as2, ad2, N);
    k_agg2<<<(N + AGG2_WARPS - 1) / AGG2_WARPS, AGG2_WARPS * 32>>>(b2, W3, N);

    // layer 3 (alphas inline)
    k_agg3<<<(N + 7) / 8, 256>>>(a3s, a3d, b3, out, N);
}